// round 7
// baseline (speedup 1.0000x reference)
#include <cuda_runtime.h>
#include <cuda_fp16.h>
#include <cstdint>

// ============================================================================
// LinearCapsPro:  out[b,c] = sqrt( u_c^T (W_c W_c^T + eps I)^{-1} u_c ),
//                 u_c = W_c x_b
// Restructured:   G_c = R_c R_c^T (Cholesky)  =>  out[b,c] = || (R_c^{-1} W_c) x_b ||
// Prep W' = R^{-1} W (tiny), then ONE fp16 GEMM y = x @ W'^T with a fused
// sum-of-squares + sqrt epilogue (y never touches memory).
//
// R6: 280.9us; GEMM at ~92% of legacy fp16-mma issue ceiling. R7: persistent
// CTAs with a continuous cp.async ring across tiles (hide per-wave pipeline
// fill + overlap epilogue with next tile's loads) + merged concurrent prep.
// ============================================================================

#define BATCH 8192
#define KDIM 512
#define NTOT 8192          // C*D
#define NUM_CAPS 1024
#define EPS_REG 1e-4f

#define BM 128
#define BN 256
#define BK 64              // 64 fp16 = 128B rows
#define STAGES 4
#define KPT 8              // k-iters per tile (512/64)
#define GRIDX 148          // persistent CTAs (1 per SM)
#define NTILES 2048        // (8192/128) * (8192/256)

#define A_BYTES (BM * BK * 2)           // 16384
#define B_BYTES (BN * BK * 2)           // 32768
#define STAGE_BYTES (A_BYTES + B_BYTES) // 49152
#define SMEM_TOTAL (STAGES * STAGE_BYTES) // 196608

// Scratch (static device globals: allocation-free per harness rules).
// fp16, "fragment-order" permuted k layout within each 32-k block:
//   k = 32*blk + 16h + 8u + 2t + e  ->  p = 32*blk + 8t + 4h + 2u + e
__device__ __align__(256) __half g_xh[BATCH * KDIM];
__device__ __align__(256) __half g_wph[NTOT * KDIM];

// ---------------------------------------------------------------------------
__device__ __forceinline__ int permh(int k) {
    return (k & ~31) | (((k >> 1) & 3) << 3) | (((k >> 4) & 1) << 2)
         | (((k >> 3) & 1) << 1) | (k & 1);
}

__device__ __forceinline__ uint32_t smem_u32(const void* p) {
    uint32_t a;
    asm("{ .reg .u64 t; cvta.to.shared.u64 t, %1; cvt.u32.u64 %0, t; }"
        : "=r"(a) : "l"(p));
    return a;
}

__device__ __forceinline__ void cp_async16(uint32_t dst, const void* src) {
    asm volatile("cp.async.cg.shared.global [%0], [%1], 16;"
                 :: "r"(dst), "l"(src) : "memory");
}
__device__ __forceinline__ void cp_commit() {
    asm volatile("cp.async.commit_group;" ::: "memory");
}
__device__ __forceinline__ void cp_wait2() {
    asm volatile("cp.async.wait_group 2;" ::: "memory");
}

__device__ __forceinline__ void lds128u(uint4& v, uint32_t addr) {
    asm volatile("ld.shared.v4.u32 {%0,%1,%2,%3}, [%4];"
                 : "=r"(v.x), "=r"(v.y), "=r"(v.z), "=r"(v.w)
                 : "r"(addr));
}

// m16n8k16 fp16 MMA, fp32 accumulate.
__device__ __forceinline__ void mma_f16(float* c,
                                        uint32_t a0, uint32_t a1,
                                        uint32_t a2, uint32_t a3,
                                        uint32_t b0, uint32_t b1) {
    asm volatile(
        "mma.sync.aligned.m16n8k16.row.col.f32.f16.f16.f32 "
        "{%0,%1,%2,%3}, {%4,%5,%6,%7}, {%8,%9}, {%0,%1,%2,%3};"
        : "+f"(c[0]), "+f"(c[1]), "+f"(c[2]), "+f"(c[3])
        : "r"(a0), "r"(a1), "r"(a2), "r"(a3), "r"(b0), "r"(b1));
}

// ---------------------------------------------------------------------------
// Merged prep: blocks [0,4096) convert x -> fp16 permuted; blocks
// [4096,5120) do per-capsule gram + Cholesky + W' = R^{-1} W (fp16 permuted).
// One launch -> the two independent phases run concurrently.
// ---------------------------------------------------------------------------
__global__ __launch_bounds__(256) void prep_kernel(const float4* __restrict__ x4,
                                                   const float* __restrict__ w) {
    __shared__ float sW[8][516];
    __shared__ float sG[8][8];
    __shared__ float sR[8][8];
    __shared__ float sRinv[8];

    int tid = threadIdx.x;
    if (blockIdx.x < 4096) {
        // ---- convert x ----
        int i = blockIdx.x * 256 + tid;       // covers BATCH*KDIM/4 exactly
        float4 v = x4[i];
        int row = i >> 7;                     // 128 float4 per row
        int k = (i & 127) << 2;
        __half2* dst = reinterpret_cast<__half2*>(g_xh + (size_t)row * KDIM);
        dst[permh(k) >> 1]     = __floats2half2_rn(v.x, v.y);
        dst[permh(k + 2) >> 1] = __floats2half2_rn(v.z, v.w);
        return;
    }

    // ---- per-capsule W prep ----
    int c = blockIdx.x - 4096;
    for (int i = tid; i < 8 * 512; i += 256)
        sW[i >> 9][i & 511] = w[c * 4096 + i];
    __syncthreads();

    {   // gram: 4 threads per (d,e) pair, quad shuffle reduce
        int p = tid >> 2, sub = tid & 3;
        int d = p >> 3, e = p & 7;
        float s = 0.f;
        #pragma unroll 8
        for (int k = sub * 128; k < sub * 128 + 128; k++)
            s += sW[d][k] * sW[e][k];
        s += __shfl_xor_sync(0xffffffffu, s, 1);
        s += __shfl_xor_sync(0xffffffffu, s, 2);
        if (sub == 0) sG[d][e] = s + (d == e ? EPS_REG : 0.f);
    }
    __syncthreads();

    if (tid == 0) {
        float R[8][8];
        #pragma unroll
        for (int i = 0; i < 8; i++) {
            #pragma unroll
            for (int j = 0; j <= i; j++) {
                float s = sG[i][j];
                for (int k = 0; k < j; k++) s -= R[i][k] * R[j][k];
                if (i == j) R[i][i] = sqrtf(s);
                else        R[i][j] = s / R[j][j];
            }
        }
        #pragma unroll
        for (int i = 0; i < 8; i++) {
            sRinv[i] = 1.0f / R[i][i];
            #pragma unroll
            for (int j = 0; j <= i; j++) sR[i][j] = R[i][j];
        }
    }
    __syncthreads();

    for (int k = tid; k < 512; k += 256) {
        float y[8];
        #pragma unroll
        for (int d = 0; d < 8; d++) {
            float t = sW[d][k];
            #pragma unroll
            for (int j = 0; j < 8; j++)
                if (j < d) t -= sR[d][j] * y[j];
            y[d] = t * sRinv[d];
        }
        int pk = permh(k);
        #pragma unroll
        for (int d = 0; d < 8; d++)
            g_wph[(size_t)(c * 8 + d) * KDIM + pk] = __float2half_rn(y[d]);
    }
}

// ---------------------------------------------------------------------------
// Persistent GEMM: 148 CTAs, each owns tiles t = bid + i*148 (128x256 each).
// ONE continuous 4-stage cp.async ring across all of a CTA's tiles: global
// iteration gi = tileIdx*8 + kk. Producer stays 3 stages ahead, crossing tile
// boundaries, so pipeline fill is paid once per CTA and each tile's epilogue
// overlaps the next tile's loads.
// ---------------------------------------------------------------------------
__global__ __launch_bounds__(256, 1) void caps_gemm_kernel(float* __restrict__ out) {
    extern __shared__ char smem[];
    const uint32_t sbase = smem_u32(smem);
    const int tid = threadIdx.x;
    const int lane = tid & 31;
    const int wid = tid >> 5;
    const int warp_m = wid & 1;       // 2 warps along M
    const int warp_n = wid >> 1;      // 4 warps along N
    const int g = lane >> 2;          // groupID
    const int tg = lane & 3;          // threadID_in_group
    const int bid = blockIdx.x;

    const int myTiles = (NTILES - bid + GRIDX - 1) / GRIDX;  // 13 or 14
    const int totalIters = myTiles * KPT;

    // Per-thread producer destination offsets (fixed relative to stage base).
    uint32_t dstA[4], dstB[8];
    int rowA[4], colA[4], rowB[8], colB[8];
    #pragma unroll
    for (int i = 0; i < 4; i++) {
        int ch = i * 256 + tid;               // 0..1023
        rowA[i] = ch >> 3; colA[i] = ch & 7;
        dstA[i] = (uint32_t)(rowA[i] * 128 + ((colA[i] ^ ((rowA[i] & 1) << 2)) << 4));
    }
    #pragma unroll
    for (int i = 0; i < 8; i++) {
        int ch = i * 256 + tid;               // 0..2047
        rowB[i] = ch >> 3; colB[i] = ch & 7;
        dstB[i] = (uint32_t)(A_BYTES + rowB[i] * 128 + ((colB[i] ^ ((rowB[i] & 1) << 2)) << 4));
    }

    auto issue = [&](int gi) {
        int t = bid + (gi >> 3) * GRIDX;
        int kk = gi & 7;
        int m0 = (t >> 5) * BM;
        int n0 = (t & 31) * BN;
        uint32_t st = sbase + (uint32_t)(gi & (STAGES - 1)) * STAGE_BYTES;
        const char* xa = (const char*)g_xh + (size_t)kk * 128;
        const char* wa = (const char*)g_wph + (size_t)kk * 128;
        #pragma unroll
        for (int i = 0; i < 4; i++)
            cp_async16(st + dstA[i],
                       xa + (size_t)(m0 + rowA[i]) * 1024 + colA[i] * 16);
        #pragma unroll
        for (int i = 0; i < 8; i++)
            cp_async16(st + dstB[i],
                       wa + (size_t)(n0 + rowB[i]) * 1024 + colB[i] * 16);
        cp_commit();
    };

    // Prologue: fill first 3 stages (totalIters >= 104 always).
    #pragma unroll
    for (int s = 0; s < STAGES - 1; s++) issue(s);

    float acc[4][8][4];
    #pragma unroll
    for (int mf = 0; mf < 4; mf++)
        #pragma unroll
        for (int nf = 0; nf < 8; nf++)
            #pragma unroll
            for (int r = 0; r < 4; r++) acc[mf][nf][r] = 0.f;

    // Consumer base offsets. All rows a thread touches share parity (g&1).
    uint32_t aRow[4], bRow[8];
    #pragma unroll
    for (int mf = 0; mf < 4; mf++) aRow[mf] = (warp_m * 64 + mf * 16 + g) * 128;
    #pragma unroll
    for (int nf = 0; nf < 8; nf++) bRow[nf] = A_BYTES + (warp_n * 64 + nf * 8 + g) * 128;
    const uint32_t par = (uint32_t)((g & 1) << 2);

    #pragma unroll 1
    for (int gi = 0; gi < totalIters; gi++) {
        cp_wait2();
        __syncthreads();
        if (gi + STAGES - 1 < totalIters) {
            issue(gi + STAGES - 1);
        } else {
            cp_commit();   // empty group keeps wait_group accounting exact
        }

        uint32_t st = sbase + (uint32_t)(gi & (STAGES - 1)) * STAGE_BYTES;
        #pragma unroll
        for (int b = 0; b < 2; b++) {          // two 32-k blocks per stage
            uint32_t ck = (uint32_t)(((4 * b + tg) ^ par) << 4);
            uint4 aLo[4], aHi[4];
            #pragma unroll
            for (int mf = 0; mf < 4; mf++) {
                lds128u(aLo[mf], st + aRow[mf] + ck);
                lds128u(aHi[mf], st + aRow[mf] + 1024 + ck);  // +8 rows
            }
            #pragma unroll
            for (int nfg = 0; nfg < 2; nfg++) {
                uint4 bF[4];
                #pragma unroll
                for (int q = 0; q < 4; q++)
                    lds128u(bF[q], st + bRow[nfg * 4 + q] + ck);
                #pragma unroll
                for (int mf = 0; mf < 4; mf++) {
                    #pragma unroll
                    for (int q = 0; q < 4; q++) {
                        mma_f16(acc[mf][nfg * 4 + q],
                                aLo[mf].x, aHi[mf].x, aLo[mf].y, aHi[mf].y,
                                bF[q].x, bF[q].y);
                    }
                }
                #pragma unroll
                for (int mf = 0; mf < 4; mf++) {
                    #pragma unroll
                    for (int q = 0; q < 4; q++) {
                        mma_f16(acc[mf][nfg * 4 + q],
                                aLo[mf].z, aHi[mf].z, aLo[mf].w, aHi[mf].w,
                                bF[q].z, bF[q].w);
                    }
                }
            }
        }

        if ((gi & 7) == 7) {
            // ---------------- fused epilogue for tile just finished --------
            int t = bid + (gi >> 3) * GRIDX;
            int m0 = (t >> 5) * BM;
            int n0 = (t & 31) * BN;
            const int capbase = (n0 >> 3) + warp_n * 8;
            #pragma unroll
            for (int mf = 0; mf < 4; mf++) {
                float r0[8], r1[8];
                #pragma unroll
                for (int nf = 0; nf < 8; nf++) {
                    float* c = acc[mf][nf];
                    float s0 = c[0] * c[0] + c[1] * c[1];
                    float s1 = c[2] * c[2] + c[3] * c[3];
                    s0 += __shfl_xor_sync(0xffffffffu, s0, 1);
                    s0 += __shfl_xor_sync(0xffffffffu, s0, 2);
                    s1 += __shfl_xor_sync(0xffffffffu, s1, 1);
                    s1 += __shfl_xor_sync(0xffffffffu, s1, 2);
                    r0[nf] = sqrtf(s0);
                    r1[nf] = sqrtf(s1);
                }
                if (tg == 0) {
                    int row = m0 + warp_m * 64 + mf * 16 + g;
                    float* p0 = out + (size_t)row * NUM_CAPS + capbase;
                    float* p1 = out + (size_t)(row + 8) * NUM_CAPS + capbase;
                    *reinterpret_cast<float4*>(p0)     = make_float4(r0[0], r0[1], r0[2], r0[3]);
                    *reinterpret_cast<float4*>(p0 + 4) = make_float4(r0[4], r0[5], r0[6], r0[7]);
                    *reinterpret_cast<float4*>(p1)     = make_float4(r1[0], r1[1], r1[2], r1[3]);
                    *reinterpret_cast<float4*>(p1 + 4) = make_float4(r1[4], r1[5], r1[6], r1[7]);
                }
            }
            #pragma unroll
            for (int mf = 0; mf < 4; mf++)
                #pragma unroll
                for (int nf = 0; nf < 8; nf++)
                    #pragma unroll
                    for (int r = 0; r < 4; r++) acc[mf][nf][r] = 0.f;
        }
    }
}

// ---------------------------------------------------------------------------
extern "C" void kernel_launch(void* const* d_in, const int* in_sizes, int n_in,
                              void* d_out, int out_size) {
    (void)in_sizes; (void)n_in; (void)out_size;
    const float* x = (const float*)d_in[0];
    // d_in[1] = eye (unused; eps*I applied analytically)
    const float* w = (const float*)d_in[2];
    float* out = (float*)d_out;

    prep_kernel<<<4096 + NUM_CAPS, 256>>>(
        reinterpret_cast<const float4*>(x), w);

    cudaFuncSetAttribute(caps_gemm_kernel,
                         cudaFuncAttributeMaxDynamicSharedMemorySize, SMEM_TOTAL);
    caps_gemm_kernel<<<GRIDX, 256, SMEM_TOTAL>>>(out);
}